// round 3
// baseline (speedup 1.0000x reference)
#include <cuda_runtime.h>

typedef unsigned long long u64;

#define B_  2
#define T_  2560
#define C_  768
#define H_  12
#define HD_ 64
#define M_  (B_*T_)   // 5120

// ---- scratch (static device arrays; no allocation) ----
__device__ float g_Q[B_*H_*T_*HD_];
__device__ float g_K[B_*H_*T_*HD_];
__device__ float g_V[B_*H_*T_*HD_];
__device__ float g_Y[B_*T_*C_];

// ---- packed f32x2 helpers (Blackwell FFMA2) ----
__device__ __forceinline__ u64 fma2(u64 a, u64 b, u64 c) {
    u64 d; asm("fma.rn.f32x2 %0, %1, %2, %3;" : "=l"(d) : "l"(a), "l"(b), "l"(c)); return d;
}
__device__ __forceinline__ u64 mul2(u64 a, u64 b) {
    u64 d; asm("mul.rn.f32x2 %0, %1, %2;" : "=l"(d) : "l"(a), "l"(b)); return d;
}
__device__ __forceinline__ u64 pack2(float x, float y) {
    u64 d; asm("mov.b64 %0, {%1, %2};" : "=l"(d) : "f"(x), "f"(y)); return d;
}
__device__ __forceinline__ float2 unpack2(u64 v) {
    float2 r; asm("mov.b64 {%0, %1}, %2;" : "=f"(r.x), "=f"(r.y) : "l"(v)); return r;
}
__device__ __forceinline__ float ex2f_(float x) {
    float y; asm("ex2.approx.ftz.f32 %0, %1;" : "=f"(y) : "f"(x)); return y;
}

// ============================================================================
// GEMM: out[m,n] = sum_k A[m,k] * W[n,k] + bias[n]
// MODE 0: A = x, three outputs (z selects K/Q/V weights), out layout [B,H,T,hd]
// MODE 1: A = g_Y, out layout [M, C] (final projection into d_out)
// 128x128x16 tiles, 256 threads, 8x8 microtile as f32x2 pairs.
// ============================================================================
template<int MODE>
__global__ void __launch_bounds__(256) gemm_kernel(
    const float* __restrict__ A,
    const float* __restrict__ W0, const float* __restrict__ W1, const float* __restrict__ W2,
    const float* __restrict__ bias0, const float* __restrict__ bias1, const float* __restrict__ bias2,
    float* __restrict__ outp)
{
    __shared__ float As[128][16];
    __shared__ float Bs[16][128];

    const float* W; const float* bias; float* out;
    if (MODE == 0) {
        int z = blockIdx.z;
        W    = (z==0) ? W0    : ((z==1) ? W1    : W2);
        bias = (z==0) ? bias0 : ((z==1) ? bias1 : bias2);
        out  = (z==0) ? g_K   : ((z==1) ? g_Q   : g_V);
    } else {
        W = W0; bias = bias0; out = outp;
    }
    const float* Ap = (MODE == 0) ? A : (const float*)g_Y;

    int tid = threadIdx.x;
    int tx = tid & 15, ty = tid >> 4;
    int m0 = blockIdx.y * 128, n0 = blockIdx.x * 128;

    u64 acc[8][4];
    #pragma unroll
    for (int i = 0; i < 8; i++)
        #pragma unroll
        for (int j = 0; j < 4; j++) acc[i][j] = 0ull;

    #pragma unroll 1
    for (int k0 = 0; k0 < C_; k0 += 16) {
        #pragma unroll
        for (int i = 0; i < 2; i++) {
            int id = tid + i * 256;        // 0..511
            int r = id >> 2, c4 = id & 3;  // 128 rows x 4 float4s
            *(float4*)&As[r][c4*4] = *(const float4*)&Ap[(m0 + r) * C_ + k0 + c4*4];
            float4 w = *(const float4*)&W[(n0 + r) * C_ + k0 + c4*4];
            Bs[c4*4+0][r] = w.x; Bs[c4*4+1][r] = w.y;
            Bs[c4*4+2][r] = w.z; Bs[c4*4+3][r] = w.w;
        }
        __syncthreads();
        #pragma unroll
        for (int k = 0; k < 16; k++) {
            ulonglong2 b01 = *(const ulonglong2*)&Bs[k][tx*8];
            ulonglong2 b23 = *(const ulonglong2*)&Bs[k][tx*8 + 4];
            #pragma unroll
            for (int i = 0; i < 8; i++) {
                float a = As[ty*8 + i][k];
                u64 a2 = pack2(a, a);
                acc[i][0] = fma2(a2, b01.x, acc[i][0]);
                acc[i][1] = fma2(a2, b01.y, acc[i][1]);
                acc[i][2] = fma2(a2, b23.x, acc[i][2]);
                acc[i][3] = fma2(a2, b23.y, acc[i][3]);
            }
        }
        __syncthreads();
    }

    int n_base = n0 + tx * 8;
    float4 bb0 = *(const float4*)&bias[n_base];
    float4 bb1 = *(const float4*)&bias[n_base + 4];
    #pragma unroll
    for (int i = 0; i < 8; i++) {
        int mm = m0 + ty*8 + i;
        float* p;
        if (MODE == 0) {
            int bi = mm / T_;
            int tq = mm - bi * T_;
            int h = n_base >> 6, d = n_base & 63;
            p = out + ((((bi * H_) + h) * T_ + tq) << 6) + d;   // [B,H,T,hd]
        } else {
            p = out + (size_t)mm * C_ + n_base;                 // [M,C]
        }
        float2 v0 = unpack2(acc[i][0]), v1 = unpack2(acc[i][1]);
        float2 v2 = unpack2(acc[i][2]), v3 = unpack2(acc[i][3]);
        *(float4*)p       = make_float4(v0.x + bb0.x, v0.y + bb0.y, v1.x + bb0.z, v1.y + bb0.w);
        *(float4*)(p + 4) = make_float4(v2.x + bb1.x, v2.y + bb1.y, v3.x + bb1.z, v3.y + bb1.w);
    }
}

// ============================================================================
// Attention: one query row per thread, 128 rows per block, online softmax
// over 16-key chunks. Mask: (q%256) >= (k%256). Fully-masked chunks skipped
// at block granularity. Scale (1/8) and log2e folded into q.
// Output written as [B, T, H*hd] = [B,T,C] into g_Y.
// ============================================================================
__global__ void __launch_bounds__(128) attn_kernel()
{
    __shared__ __align__(16) float Ks[16 * 64];
    __shared__ __align__(16) float Vs[16 * 64];

    int tid = threadIdx.x;
    int bh = blockIdx.y;                      // 0..23 = b*12+h
    int qglob = blockIdx.x * 128 + tid;       // 0..2559
    const float* qptr  = g_Q + ((size_t)bh * T_ + qglob) * HD_;
    const float* Kbase = g_K + (size_t)bh * T_ * HD_;
    const float* Vbase = g_V + (size_t)bh * T_ * HD_;

    const float SC = 0.125f * 1.4426950408889634f;   // (1/sqrt(64)) * log2(e)
    u64 q2[32];
    #pragma unroll
    for (int i = 0; i < 16; i++) {
        float4 v = *(const float4*)&qptr[i * 4];
        q2[2*i]   = pack2(v.x * SC, v.y * SC);
        q2[2*i+1] = pack2(v.z * SC, v.w * SC);
    }
    u64 acc[32];
    #pragma unroll
    for (int i = 0; i < 32; i++) acc[i] = 0ull;
    float m = -1e30f, l = 0.0f;
    int r  = qglob & 255;                       // within-tile query row
    int r0 = (blockIdx.x * 128) & 255;          // 0 or 128 (block base row)

    #pragma unroll 1
    for (int k0 = 0; k0 < T_; k0 += 16) {
        int c0 = k0 & 255;                      // within-tile key col base
        if (c0 >= r0 + 128) continue;           // whole chunk masked for this block

        #pragma unroll
        for (int i = 0; i < 2; i++) {
            int id = tid + i * 128;             // 0..255 float4s = 16x64 floats
            ((float4*)Ks)[id] = *(const float4*)&Kbase[k0 * HD_ + id * 4];
            ((float4*)Vs)[id] = *(const float4*)&Vbase[k0 * HD_ + id * 4];
        }
        __syncthreads();

        // scores for 16 keys
        float s[16];
        float cmax = -1e30f;
        #pragma unroll
        for (int j = 0; j < 16; j++) {
            const ulonglong2* kr = (const ulonglong2*)(Ks + j * 64);
            u64 a0 = 0ull, a1 = 0ull;
            #pragma unroll
            for (int d4 = 0; d4 < 16; d4++) {
                ulonglong2 kk = kr[d4];
                a0 = fma2(q2[2*d4],   kk.x, a0);
                a1 = fma2(q2[2*d4+1], kk.y, a1);
            }
            float2 f0 = unpack2(a0), f1 = unpack2(a1);
            float sj = (f0.x + f0.y) + (f1.x + f1.y);
            sj = (c0 + j <= r) ? sj : -1e30f;   // per-row mask
            s[j] = sj;
            cmax = fmaxf(cmax, sj);
        }

        float mnew = fmaxf(m, cmax);
        float corr = ex2f_(m - mnew);
        l *= corr;
        u64 c2 = pack2(corr, corr);
        #pragma unroll
        for (int d2 = 0; d2 < 32; d2++) acc[d2] = mul2(acc[d2], c2);
        m = mnew;

        #pragma unroll
        for (int j = 0; j < 16; j++) {
            float p = ex2f_(s[j] - m);
            l += p;
            u64 p2 = pack2(p, p);
            const ulonglong2* vr = (const ulonglong2*)(Vs + j * 64);
            #pragma unroll
            for (int d4 = 0; d4 < 16; d4++) {
                ulonglong2 vv = vr[d4];
                acc[2*d4]   = fma2(p2, vv.x, acc[2*d4]);
                acc[2*d4+1] = fma2(p2, vv.y, acc[2*d4+1]);
            }
        }
        __syncthreads();
    }

    float inv = 1.0f / l;
    int b = bh / H_, h = bh - b * H_;
    float* yp = g_Y + ((size_t)b * T_ + qglob) * C_ + h * HD_;
    #pragma unroll
    for (int d2 = 0; d2 < 32; d2 += 2) {
        float2 v0 = unpack2(acc[d2]), v1 = unpack2(acc[d2+1]);
        *(float4*)&yp[d2 * 2] = make_float4(v0.x * inv, v0.y * inv, v1.x * inv, v1.y * inv);
    }
}

// ============================================================================
extern "C" void kernel_launch(void* const* d_in, const int* in_sizes, int n_in,
                              void* d_out, int out_size)
{
    (void)in_sizes; (void)n_in; (void)out_size;
    const float* x  = (const float*)d_in[0];
    const float* Wk = (const float*)d_in[1];
    const float* bk = (const float*)d_in[2];
    const float* Wq = (const float*)d_in[3];
    const float* bq = (const float*)d_in[4];
    const float* Wv = (const float*)d_in[5];
    const float* bv = (const float*)d_in[6];
    const float* Wp = (const float*)d_in[7];
    const float* bp = (const float*)d_in[8];
    float* out = (float*)d_out;

    // K/Q/V projections: grid z selects which; writes g_K/g_Q/g_V in [B,H,T,hd]
    gemm_kernel<0><<<dim3(C_/128, M_/128, 3), 256>>>(x, Wk, Wq, Wv, bk, bq, bv, nullptr);
    // fused masked attention -> g_Y in [B,T,C]
    attn_kernel<<<dim3(T_/128, B_*H_), 128>>>();
    // output projection -> d_out
    gemm_kernel<1><<<dim3(C_/128, M_/128, 1), 256>>>(nullptr, Wp, Wp, Wp, bp, bp, bp, out);
}

// round 6
// speedup vs baseline: 1.2475x; 1.2475x over previous
#include <cuda_runtime.h>

typedef unsigned long long u64;

#define B_  2
#define T_  2560
#define C_  768
#define H_  12
#define HD_ 64
#define M_  (B_*T_)   // 5120

// ---- scratch (static device arrays; no allocation) ----
__device__ float g_Q[B_*H_*T_*HD_];
__device__ float g_K[B_*H_*T_*HD_];
__device__ float g_V[B_*H_*T_*HD_];
__device__ float g_Y[B_*T_*C_];

// ---- packed f32x2 helpers (Blackwell FFMA2) ----
__device__ __forceinline__ u64 fma2(u64 a, u64 b, u64 c) {
    u64 d; asm("fma.rn.f32x2 %0, %1, %2, %3;" : "=l"(d) : "l"(a), "l"(b), "l"(c)); return d;
}
__device__ __forceinline__ u64 add2_(u64 a, u64 b) {
    u64 d; asm("add.rn.f32x2 %0, %1, %2;" : "=l"(d) : "l"(a), "l"(b)); return d;
}
__device__ __forceinline__ u64 pack2(float x, float y) {
    u64 d; asm("mov.b64 %0, {%1, %2};" : "=l"(d) : "f"(x), "f"(y)); return d;
}
__device__ __forceinline__ float2 unpack2(u64 v) {
    float2 r; asm("mov.b64 {%0, %1}, %2;" : "=f"(r.x), "=f"(r.y) : "l"(v)); return r;
}
__device__ __forceinline__ float ex2f_(float x) {
    float y; asm("ex2.approx.ftz.f32 %0, %1;" : "=f"(y) : "f"(x)); return y;
}

// ============================================================================
// GEMM: out[m,n] = sum_k A[m,k] * W[n,k] + bias[n]
// MODE 0: A = x, three outputs (z selects K/Q/V weights), out layout [B,H,T,hd]
// MODE 1: A = g_Y, out layout [M, C] (final projection into d_out)
// 128x128x16 tiles, 256 threads, 8x8 microtile as f32x2 pairs.
// Register-prefetch of next K-tile; 2 blocks/SM.
// ============================================================================
template<int MODE>
__global__ void __launch_bounds__(256, 2) gemm_kernel(
    const float* __restrict__ A,
    const float* __restrict__ W0, const float* __restrict__ W1, const float* __restrict__ W2,
    const float* __restrict__ bias0, const float* __restrict__ bias1, const float* __restrict__ bias2,
    float* __restrict__ outp)
{
    __shared__ float As[128][16];
    __shared__ float Bs[16][128];

    const float* W; const float* bias; float* out;
    if (MODE == 0) {
        int z = blockIdx.z;
        W    = (z==0) ? W0    : ((z==1) ? W1    : W2);
        bias = (z==0) ? bias0 : ((z==1) ? bias1 : bias2);
        out  = (z==0) ? g_K   : ((z==1) ? g_Q   : g_V);
    } else {
        W = W0; bias = bias0; out = outp;
    }
    const float* Ap = (MODE == 0) ? A : (const float*)g_Y;

    int tid = threadIdx.x;
    int tx = tid & 15, ty = tid >> 4;
    int m0 = blockIdx.y * 128, n0 = blockIdx.x * 128;

    u64 acc[8][4];
    #pragma unroll
    for (int i = 0; i < 8; i++)
        #pragma unroll
        for (int j = 0; j < 4; j++) acc[i][j] = 0ull;

    // per-thread load coordinates
    int r0_ = tid >> 2,            c4_0 = tid & 3;
    int r1_ = (tid + 256) >> 2,    c4_1 = (tid + 256) & 3;

    float4 fA0, fA1, fW0, fW1;
    fA0 = *(const float4*)&Ap[(m0 + r0_) * C_ + c4_0 * 4];
    fW0 = *(const float4*)&W [(n0 + r0_) * C_ + c4_0 * 4];
    fA1 = *(const float4*)&Ap[(m0 + r1_) * C_ + c4_1 * 4];
    fW1 = *(const float4*)&W [(n0 + r1_) * C_ + c4_1 * 4];

    #pragma unroll 1
    for (int k0 = 0; k0 < C_; k0 += 16) {
        *(float4*)&As[r0_][c4_0*4] = fA0;
        Bs[c4_0*4+0][r0_] = fW0.x; Bs[c4_0*4+1][r0_] = fW0.y;
        Bs[c4_0*4+2][r0_] = fW0.z; Bs[c4_0*4+3][r0_] = fW0.w;
        *(float4*)&As[r1_][c4_1*4] = fA1;
        Bs[c4_1*4+0][r1_] = fW1.x; Bs[c4_1*4+1][r1_] = fW1.y;
        Bs[c4_1*4+2][r1_] = fW1.z; Bs[c4_1*4+3][r1_] = fW1.w;
        __syncthreads();

        if (k0 + 16 < C_) {
            fA0 = *(const float4*)&Ap[(m0 + r0_) * C_ + k0 + 16 + c4_0 * 4];
            fW0 = *(const float4*)&W [(n0 + r0_) * C_ + k0 + 16 + c4_0 * 4];
            fA1 = *(const float4*)&Ap[(m0 + r1_) * C_ + k0 + 16 + c4_1 * 4];
            fW1 = *(const float4*)&W [(n0 + r1_) * C_ + k0 + 16 + c4_1 * 4];
        }

        #pragma unroll
        for (int k = 0; k < 16; k++) {
            ulonglong2 b01 = *(const ulonglong2*)&Bs[k][tx*8];
            ulonglong2 b23 = *(const ulonglong2*)&Bs[k][tx*8 + 4];
            #pragma unroll
            for (int i = 0; i < 8; i++) {
                float a = As[ty*8 + i][k];
                u64 a2 = pack2(a, a);
                acc[i][0] = fma2(a2, b01.x, acc[i][0]);
                acc[i][1] = fma2(a2, b01.y, acc[i][1]);
                acc[i][2] = fma2(a2, b23.x, acc[i][2]);
                acc[i][3] = fma2(a2, b23.y, acc[i][3]);
            }
        }
        __syncthreads();
    }

    int n_base = n0 + tx * 8;
    float4 bb0 = *(const float4*)&bias[n_base];
    float4 bb1 = *(const float4*)&bias[n_base + 4];
    #pragma unroll
    for (int i = 0; i < 8; i++) {
        int mm = m0 + ty*8 + i;
        float* p;
        if (MODE == 0) {
            int bi = mm / T_;
            int tq = mm - bi * T_;
            int h = n_base >> 6, d = n_base & 63;
            p = out + ((((bi * H_) + h) * T_ + tq) << 6) + d;   // [B,H,T,hd]
        } else {
            p = out + (size_t)mm * C_ + n_base;                 // [M,C]
        }
        float2 v0 = unpack2(acc[i][0]), v1 = unpack2(acc[i][1]);
        float2 v2 = unpack2(acc[i][2]), v3 = unpack2(acc[i][3]);
        *(float4*)p       = make_float4(v0.x + bb0.x, v0.y + bb0.y, v1.x + bb0.z, v1.y + bb0.w);
        *(float4*)(p + 4) = make_float4(v2.x + bb1.x, v2.y + bb1.y, v3.x + bb1.z, v3.y + bb1.w);
    }
}

// ============================================================================
// Attention (no-max softmax; mask (q%256) >= (k%256)).
// Block = 128 threads = 64 thread-pairs. Pair (t, t^1) handles query rows
// {p, p+128} of one 256-tile; thread half = t&1 owns dims [half*32, half*32+32).
// Keys streamed in 16-key chunks, double-buffered smem, 1 sync/chunk.
// Warp-uniform skip of fully-masked chunk work.
// ============================================================================
template<bool DOA>
__device__ __forceinline__ void chunk_compute(
    const float* Ksb, const float* Vsb, int c0, int half, int ra, int rb,
    const u64 (&q2a)[16], const u64 (&q2b)[16],
    u64 (&acca)[16], u64 (&accb)[16], float& la, float& lb)
{
    #pragma unroll
    for (int j = 0; j < 16; j++) {
        const ulonglong2* kr = (const ulonglong2*)(Ksb + j*64 + half*32);
        u64 a0 = 0ull, a1 = 0ull, b0 = 0ull, b1 = 0ull;
        #pragma unroll
        for (int d = 0; d < 8; d++) {
            ulonglong2 kk = kr[d];
            if (DOA) {
                a0 = fma2(q2a[2*d],   kk.x, a0);
                a1 = fma2(q2a[2*d+1], kk.y, a1);
            }
            b0 = fma2(q2b[2*d],   kk.x, b0);
            b1 = fma2(q2b[2*d+1], kk.y, b1);
        }
        float sb; { float2 f = unpack2(add2_(b0, b1)); sb = f.x + f.y; }
        float sa = 0.f;
        if (DOA) { float2 f = unpack2(add2_(a0, a1)); sa = f.x + f.y; }
        sb += __shfl_xor_sync(0xffffffffu, sb, 1);
        if (DOA) sa += __shfl_xor_sync(0xffffffffu, sa, 1);
        int kc = c0 + j;
        float pb = (rb >= kc) ? ex2f_(sb) : 0.f;
        float pa = 0.f;
        if (DOA) pa = (ra >= kc) ? ex2f_(sa) : 0.f;
        lb += pb;
        if (DOA) la += pa;
        u64 pb2 = pack2(pb, pb);
        u64 pa2 = 0ull;
        if (DOA) pa2 = pack2(pa, pa);
        const ulonglong2* vr = (const ulonglong2*)(Vsb + j*64 + half*32);
        #pragma unroll
        for (int d = 0; d < 8; d++) {
            ulonglong2 vv = vr[d];
            if (DOA) {
                acca[2*d]   = fma2(pa2, vv.x, acca[2*d]);
                acca[2*d+1] = fma2(pa2, vv.y, acca[2*d+1]);
            }
            accb[2*d]   = fma2(pb2, vv.x, accb[2*d]);
            accb[2*d+1] = fma2(pb2, vv.y, accb[2*d+1]);
        }
    }
}

__global__ void __launch_bounds__(128, 3) attn_kernel()
{
    __shared__ __align__(16) float Ks[2][16*64];
    __shared__ __align__(16) float Vs[2][16*64];

    const int tid  = threadIdx.x;
    const int bh   = blockIdx.y;           // b*12 + h
    const int ti   = blockIdx.x >> 1;      // tile 0..9
    const int s    = blockIdx.x & 1;       // low/high 64 pairs of the tile
    const int pl   = tid >> 1;             // pair index 0..63
    const int half = tid & 1;
    const int p    = s*64 + pl;            // row in tile, 0..127
    const int ra   = p, rb = p + 128;
    const int qa   = ti*256 + ra, qb = ti*256 + rb;
    const int pwhi = s*64 + ((tid >> 5) << 4) + 15;  // max p in this warp

    const float* Qb = g_Q + (size_t)bh * T_ * HD_;
    const float* Kb = g_K + (size_t)bh * T_ * HD_;
    const float* Vb = g_V + (size_t)bh * T_ * HD_;

    const float SC = 0.125f * 1.4426950408889634f;  // (1/sqrt(64)) * log2(e)
    u64 q2a[16], q2b[16];
    {
        const float* pa_ = Qb + (size_t)qa * HD_ + half * 32;
        const float* pb_ = Qb + (size_t)qb * HD_ + half * 32;
        #pragma unroll
        for (int i = 0; i < 8; i++) {
            float4 v = *(const float4*)&pa_[i*4];
            q2a[2*i]   = pack2(v.x*SC, v.y*SC);
            q2a[2*i+1] = pack2(v.z*SC, v.w*SC);
            float4 w = *(const float4*)&pb_[i*4];
            q2b[2*i]   = pack2(w.x*SC, w.y*SC);
            q2b[2*i+1] = pack2(w.z*SC, w.w*SC);
        }
    }
    u64 acca[16], accb[16];
    #pragma unroll
    for (int i = 0; i < 16; i++) { acca[i] = 0ull; accb[i] = 0ull; }
    float la = 0.f, lb = 0.f;

    // Chunk schedule: s==0 blocks only need c0 < 192 (rows <= 191): 12 chunks/tile.
    const int NC  = (s == 0) ? 12 : 16;
    const int NCH = 10 * NC;

    // load chunk 0
    {
        int kg = 0;
        #pragma unroll
        for (int i = 0; i < 2; i++) {
            int id = tid + i*128;
            ((float4*)Ks[0])[id] = *(const float4*)&Kb[(size_t)kg*HD_ + id*4];
            ((float4*)Vs[0])[id] = *(const float4*)&Vb[(size_t)kg*HD_ + id*4];
        }
    }
    __syncthreads();

    #pragma unroll 1
    for (int u = 0; u < NCH; u++) {
        int cb = u & 1;
        if (u + 1 < NCH) {
            int u1 = u + 1;
            int kt1 = u1 / NC;
            int c01 = (u1 - kt1 * NC) * 16;
            int kg  = kt1 * 256 + c01;
            #pragma unroll
            for (int i = 0; i < 2; i++) {
                int id = tid + i*128;
                ((float4*)Ks[cb^1])[id] = *(const float4*)&Kb[(size_t)kg*HD_ + id*4];
                ((float4*)Vs[cb^1])[id] = *(const float4*)&Vb[(size_t)kg*HD_ + id*4];
            }
        }
        int kt = u / NC;
        int c0 = (u - kt * NC) * 16;
        if (c0 <= pwhi) {
            chunk_compute<true >(Ks[cb], Vs[cb], c0, half, ra, rb, q2a, q2b, acca, accb, la, lb);
        } else if (c0 <= pwhi + 128) {
            chunk_compute<false>(Ks[cb], Vs[cb], c0, half, ra, rb, q2a, q2b, acca, accb, la, lb);
        }
        __syncthreads();
    }

    float inva = 1.0f / la;
    float invb = 1.0f / lb;
    int b = bh / H_, h = bh - (bh / H_) * H_;
    float* ya = g_Y + ((size_t)(b * T_ + qa)) * C_ + h * HD_ + half * 32;
    float* yb = g_Y + ((size_t)(b * T_ + qb)) * C_ + h * HD_ + half * 32;
    #pragma unroll
    for (int d = 0; d < 8; d++) {
        float2 v0 = unpack2(acca[2*d]), v1 = unpack2(acca[2*d+1]);
        *(float4*)&ya[d*4] = make_float4(v0.x*inva, v0.y*inva, v1.x*inva, v1.y*inva);
        float2 w0 = unpack2(accb[2*d]), w1 = unpack2(accb[2*d+1]);
        *(float4*)&yb[d*4] = make_float4(w0.x*invb, w0.y*invb, w1.x*invb, w1.y*invb);
    }
}

// ============================================================================
extern "C" void kernel_launch(void* const* d_in, const int* in_sizes, int n_in,
                              void* d_out, int out_size)
{
    (void)in_sizes; (void)n_in; (void)out_size;
    const float* x  = (const float*)d_in[0];
    const float* Wk = (const float*)d_in[1];
    const float* bk = (const float*)d_in[2];
    const float* Wq = (const float*)d_in[3];
    const float* bq = (const float*)d_in[4];
    const float* Wv = (const float*)d_in[5];
    const float* bv = (const float*)d_in[6];
    const float* Wp = (const float*)d_in[7];
    const float* bp = (const float*)d_in[8];
    float* out = (float*)d_out;

    gemm_kernel<0><<<dim3(C_/128, M_/128, 3), 256>>>(x, Wk, Wq, Wv, bk, bq, bv, nullptr);
    attn_kernel<<<dim3(20, B_*H_), 128>>>();
    gemm_kernel<1><<<dim3(C_/128, M_/128, 1), 256>>>(nullptr, Wp, Wp, Wp, bp, bp, bp, out);
}